// round 1
// baseline (speedup 1.0000x reference)
#include <cuda_runtime.h>
#include <math.h>

// Problem constants
#define BD   2
#define TT   1024
#define DD   512
#define NH   8
#define HDIM 64
#define CHK  64
#define NCH  16
#define T2   512   // half length (parity split)

// ---------------- scratch (device globals; no allocation allowed) ----------------
__device__ float g_vfilt[T2 * DD];          // 2*phi_proj at even s: [s2][r]
__device__ float g_uproj[BD * TT * DD];
__device__ float g_w[BD * TT * DD];         // conv output
__device__ float g_xt[BD * TT * DD];        // layernorm output
__device__ float g_q[BD * TT * DD];
__device__ float g_k[BD * TT * DD];
__device__ float g_v[BD * TT * DD];
__device__ float g_gate[BD * TT * DD];
__device__ float g_y[BD * TT * DD];
__device__ float g_comb[BD * TT * DD];
__device__ float g_state[BD * NH * NCH * HDIM * HDIM]; // chunk KV states

// ---------------- activation helpers ----------------
__device__ __forceinline__ float gelu_tanh(float v) {
    float c = 0.7978845608028654f;
    float t = tanhf(c * (v + 0.044715f * v * v * v));
    return 0.5f * v * (1.0f + t);
}
__device__ __forceinline__ float sigm(float v) {
    return 1.0f / (1.0f + expf(-v));
}

// ---------------- phi kernel: Vfilt[s2][r] = 2 * sum_k sf[2*s2,k]*Mf[k,r] ----------------
__global__ void phi_kernel(const float* __restrict__ sf, const float* __restrict__ mf) {
    int idx = blockIdx.x * blockDim.x + threadIdx.x;   // over 512*512
    if (idx >= T2 * DD) return;
    int s2 = idx >> 9;
    int r  = idx & 511;
    const float* srow = sf + (size_t)(2 * s2) * 24;
    float acc = 0.f;
#pragma unroll
    for (int k = 0; k < 24; k++) acc += srow[k] * mf[k * DD + r];
    g_vfilt[idx] = 2.0f * acc;
}

// ---------------- GEMM: C = act(A @ op(B) + bias) ----------------
// A: MxK row-major.  TRANSB=false: B is KxN row-major.  TRANSB=true: B is NxK (weights),
// computing A @ B^T.  BM=128, BN=64, BK=16, 256 threads, 8x4 microtile.
template<bool TRANSB, int ACT>  // ACT: 0 none, 1 gelu, 2 sigmoid
__global__ void gemm_kernel(const float* __restrict__ A, const float* __restrict__ Bm,
                            const float* __restrict__ bias, float* __restrict__ C,
                            int M, int N, int K) {
    __shared__ float As[16][132];   // transposed A tile: As[k][m]
    __shared__ float Bs[16][68];    // Bs[k][n]
    int tx = threadIdx.x;           // 0..255
    int tn = tx & 15, tm = tx >> 4;
    int m0 = blockIdx.y * 128, n0 = blockIdx.x * 64;
    float acc[8][4];
#pragma unroll
    for (int i = 0; i < 8; i++)
#pragma unroll
        for (int j = 0; j < 4; j++) acc[i][j] = 0.f;

    for (int k0 = 0; k0 < K; k0 += 16) {
        // A tile: 128x16 = 512 float4 loads, 2 per thread
#pragma unroll
        for (int l = 0; l < 2; l++) {
            int idx = tx + l * 256;
            int row = idx >> 2;
            int kq  = (idx & 3) * 4;
            float4 a = *(const float4*)&A[(size_t)(m0 + row) * K + k0 + kq];
            As[kq + 0][row] = a.x; As[kq + 1][row] = a.y;
            As[kq + 2][row] = a.z; As[kq + 3][row] = a.w;
        }
        if (!TRANSB) {
            int row = tx >> 4;            // k within tile
            int nq  = (tx & 15) * 4;
            float4 b = *(const float4*)&Bm[(size_t)(k0 + row) * N + n0 + nq];
            *(float4*)&Bs[row][nq] = b;
        } else {
            int nn = tx >> 2;             // 0..63
            int kq = (tx & 3) * 4;
            float4 b = *(const float4*)&Bm[(size_t)(n0 + nn) * K + k0 + kq];
            Bs[kq + 0][nn] = b.x; Bs[kq + 1][nn] = b.y;
            Bs[kq + 2][nn] = b.z; Bs[kq + 3][nn] = b.w;
        }
        __syncthreads();
#pragma unroll
        for (int kk = 0; kk < 16; kk++) {
            float4 a0 = *(float4*)&As[kk][tm * 8];
            float4 a1 = *(float4*)&As[kk][tm * 8 + 4];
            float4 bv = *(float4*)&Bs[kk][tn * 4];
            float aa[8] = {a0.x, a0.y, a0.z, a0.w, a1.x, a1.y, a1.z, a1.w};
            float bb[4] = {bv.x, bv.y, bv.z, bv.w};
#pragma unroll
            for (int i = 0; i < 8; i++)
#pragma unroll
                for (int j = 0; j < 4; j++) acc[i][j] += aa[i] * bb[j];
        }
        __syncthreads();
    }
    // epilogue
#pragma unroll
    for (int i = 0; i < 8; i++) {
        int m = m0 + tm * 8 + i;
        int n = n0 + tn * 4;
        float4 o;
        float vv[4];
#pragma unroll
        for (int j = 0; j < 4; j++) {
            float v = acc[i][j];
            if (bias) v += bias[n + j];
            if (ACT == 1) v = gelu_tanh(v);
            else if (ACT == 2) v = sigm(v);
            vv[j] = v;
        }
        o.x = vv[0]; o.y = vv[1]; o.z = vv[2]; o.w = vv[3];
        *(float4*)&C[(size_t)m * N + n] = o;
    }
}

// ---------------- conv kernel (parity-split causal conv, length 512) ----------------
// w_p[b,tt,r] = sum_{j<=tt} Vfilt[tt-j, r] * u[b, 2j+p, r];  output row 2*tt+p.
__global__ void conv_kernel() {
    __shared__ float us[64][64];    // 16KB
    __shared__ float vs[128][64];   // 32KB
    int rx = threadIdx.x;           // 0..63
    int ty = threadIdx.y;           // 0..3
    int r0  = blockIdx.x * 64;
    int tt0 = blockIdx.y * 64;
    int bz  = blockIdx.z;
    int b = bz >> 1, p = bz & 1;
    float acc[16];
#pragma unroll
    for (int i = 0; i < 16; i++) acc[i] = 0.f;
    const float* ub = g_uproj + (size_t)b * TT * DD;

    for (int j0 = 0; j0 <= tt0; j0 += 64) {
        for (int jj = ty; jj < 64; jj += 4)
            us[jj][rx] = ub[(size_t)(2 * (j0 + jj) + p) * DD + r0 + rx];
        int lagbase = tt0 - j0 - 63;
        for (int l = ty; l < 128; l += 4) {
            int lag = lagbase + l;
            vs[l][rx] = (lag >= 0 && lag < T2) ? g_vfilt[(size_t)lag * DD + r0 + rx] : 0.f;
        }
        __syncthreads();
#pragma unroll 4
        for (int jj = 0; jj < 64; jj++) {
            float uv = us[jj][rx];
            int base = ty * 16 + 63 - jj;
#pragma unroll
            for (int i = 0; i < 16; i++)
                acc[i] += vs[base + i][rx] * uv;
        }
        __syncthreads();
    }
#pragma unroll
    for (int i = 0; i < 16; i++) {
        int tt = tt0 + ty * 16 + i;
        g_w[((size_t)b * TT + 2 * tt + p) * DD + r0 + rx] = acc[i];
    }
}

// ---------------- layernorm over last dim (512) ----------------
__global__ void ln_kernel(const float* __restrict__ lw, const float* __restrict__ lb) {
    int row = blockIdx.x;  // 0..2047
    const float* x = g_w + (size_t)row * DD;
    float* o = g_xt + (size_t)row * DD;
    int tx = threadIdx.x;  // 128
    float4 v = *(const float4*)&x[tx * 4];
    float s  = v.x + v.y + v.z + v.w;
    float ss = v.x * v.x + v.y * v.y + v.z * v.z + v.w * v.w;
#pragma unroll
    for (int off = 16; off; off >>= 1) {
        s  += __shfl_xor_sync(0xffffffffu, s,  off);
        ss += __shfl_xor_sync(0xffffffffu, ss, off);
    }
    __shared__ float rs[4], rss[4];
    if ((tx & 31) == 0) { rs[tx >> 5] = s; rss[tx >> 5] = ss; }
    __syncthreads();
    float tot  = rs[0] + rs[1] + rs[2] + rs[3];
    float tots = rss[0] + rss[1] + rss[2] + rss[3];
    float mu  = tot * (1.0f / DD);
    float var = tots * (1.0f / DD) - mu * mu;
    float inv = rsqrtf(var + 1e-5f);
    float4 w4 = *(const float4*)&lw[tx * 4];
    float4 b4 = *(const float4*)&lb[tx * 4];
    float4 out;
    out.x = (v.x - mu) * inv * w4.x + b4.x;
    out.y = (v.y - mu) * inv * w4.y + b4.y;
    out.z = (v.z - mu) * inv * w4.z + b4.z;
    out.w = (v.w - mu) * inv * w4.w + b4.w;
    *(float4*)&o[tx * 4] = out;
}

// ---------------- attention: per-chunk local KV state ----------------
// L[b,h,c,p,n] = sum_{s in chunk} V[s,p] * K[s,n]
__global__ void attn_state_kernel() {
    __shared__ float Vs[64][65];
    __shared__ float Ks[64][65];
    int c = blockIdx.x, h = blockIdx.y, b = blockIdx.z;
    const float* Vp = g_v + ((size_t)b * TT + c * CHK) * DD + h * HDIM;
    const float* Kp = g_k + ((size_t)b * TT + c * CHK) * DD + h * HDIM;
    int tx = threadIdx.x;
    for (int idx = tx; idx < 4096; idx += 256) {
        int s = idx >> 6, q = idx & 63;
        Vs[s][q] = Vp[(size_t)s * DD + q];
        Ks[s][q] = Kp[(size_t)s * DD + q];
    }
    __syncthreads();
    int tn = tx & 15, tm = tx >> 4;
    float acc[4][4];
#pragma unroll
    for (int i = 0; i < 4; i++)
#pragma unroll
        for (int j = 0; j < 4; j++) acc[i][j] = 0.f;
    for (int s = 0; s < 64; s++) {
        float a[4], bb[4];
#pragma unroll
        for (int i = 0; i < 4; i++) a[i] = Vs[s][tm * 4 + i];
#pragma unroll
        for (int j = 0; j < 4; j++) bb[j] = Ks[s][tn * 4 + j];
#pragma unroll
        for (int i = 0; i < 4; i++)
#pragma unroll
            for (int j = 0; j < 4; j++) acc[i][j] += a[i] * bb[j];
    }
    float* Lp = g_state + (((size_t)(b * NH + h) * NCH + c) * (HDIM * HDIM));
#pragma unroll
    for (int i = 0; i < 4; i++)
#pragma unroll
        for (int j = 0; j < 4; j++)
            Lp[(tm * 4 + i) * HDIM + tn * 4 + j] = acc[i][j];
}

// ---------------- attention: exclusive prefix over chunks (in place) ----------------
__global__ void attn_scan_kernel() {
    int idx = blockIdx.x * blockDim.x + threadIdx.x;   // 65536 threads
    int bh = idx >> 12, e = idx & 4095;
    float* base = g_state + (size_t)bh * NCH * 4096 + e;
    float run = 0.f;
#pragma unroll
    for (int c = 0; c < NCH; c++) {
        float v = base[(size_t)c * 4096];
        base[(size_t)c * 4096] = run;
        run += v;
    }
}

// ---------------- attention: per-chunk output ----------------
// Y_c = Q_c @ Hprev + tril(Q_c V_c^T) @ K_c
__global__ void attn_out_kernel() {
    extern __shared__ float sm[];
    float* Qs = sm;               // [64][65]
    float* Vs = sm + 64 * 65;
    float* Ks = sm + 2 * 64 * 65;
    float* Hs = sm + 3 * 64 * 65;
    float* Ss = sm + 4 * 64 * 65;
    int c = blockIdx.x, h = blockIdx.y, b = blockIdx.z;
    int tx = threadIdx.x;
    const float* Qp = g_q + ((size_t)b * TT + c * CHK) * DD + h * HDIM;
    const float* Kp = g_k + ((size_t)b * TT + c * CHK) * DD + h * HDIM;
    const float* Vp = g_v + ((size_t)b * TT + c * CHK) * DD + h * HDIM;
    const float* Hp = g_state + (((size_t)(b * NH + h) * NCH + c) * 4096);
    for (int idx = tx; idx < 4096; idx += 256) {
        int s = idx >> 6, q = idx & 63;
        Qs[s * 65 + q] = Qp[(size_t)s * DD + q];
        Ks[s * 65 + q] = Kp[(size_t)s * DD + q];
        Vs[s * 65 + q] = Vp[(size_t)s * DD + q];
        Hs[s * 65 + q] = Hp[idx];
    }
    __syncthreads();
    int tn = tx & 15, tm = tx >> 4;
    // stage 1: S = Q V^T, causal mask (j <= i)
    {
        float acc[4][4];
#pragma unroll
        for (int i = 0; i < 4; i++)
#pragma unroll
            for (int j = 0; j < 4; j++) acc[i][j] = 0.f;
        for (int n = 0; n < 64; n++) {
            float a[4], bb[4];
#pragma unroll
            for (int i = 0; i < 4; i++) a[i] = Qs[(tm * 4 + i) * 65 + n];
#pragma unroll
            for (int j = 0; j < 4; j++) bb[j] = Vs[(tn * 4 + j) * 65 + n];
#pragma unroll
            for (int i = 0; i < 4; i++)
#pragma unroll
                for (int j = 0; j < 4; j++) acc[i][j] += a[i] * bb[j];
        }
#pragma unroll
        for (int i = 0; i < 4; i++)
#pragma unroll
            for (int j = 0; j < 4; j++) {
                int row = tm * 4 + i, col = tn * 4 + j;
                Ss[row * 65 + col] = (col <= row) ? acc[i][j] : 0.f;
            }
    }
    __syncthreads();
    // stage 2: Y = S @ K + Q @ Hprev
    float acc[4][4];
#pragma unroll
    for (int i = 0; i < 4; i++)
#pragma unroll
        for (int j = 0; j < 4; j++) acc[i][j] = 0.f;
    for (int jx = 0; jx < 64; jx++) {
        float a[4], bb[4];
#pragma unroll
        for (int i = 0; i < 4; i++) a[i] = Ss[(tm * 4 + i) * 65 + jx];
#pragma unroll
        for (int j = 0; j < 4; j++) bb[j] = Ks[jx * 65 + tn * 4 + j];
#pragma unroll
        for (int i = 0; i < 4; i++)
#pragma unroll
            for (int j = 0; j < 4; j++) acc[i][j] += a[i] * bb[j];
    }
    for (int px = 0; px < 64; px++) {
        float a[4], bb[4];
#pragma unroll
        for (int i = 0; i < 4; i++) a[i] = Qs[(tm * 4 + i) * 65 + px];
#pragma unroll
        for (int j = 0; j < 4; j++) bb[j] = Hs[px * 65 + tn * 4 + j];
#pragma unroll
        for (int i = 0; i < 4; i++)
#pragma unroll
            for (int j = 0; j < 4; j++) acc[i][j] += a[i] * bb[j];
    }
#pragma unroll
    for (int i = 0; i < 4; i++) {
        int t = c * CHK + tm * 4 + i;
#pragma unroll
        for (int j = 0; j < 4; j++)
            g_y[((size_t)b * TT + t) * DD + h * HDIM + tn * 4 + j] = acc[i][j];
    }
}

// ---------------- combine: comb = gate*Y + (1-gate)*x_tilde ----------------
__global__ void combine_kernel() {
    int idx = blockIdx.x * blockDim.x + threadIdx.x;
    if (idx >= BD * TT * DD) return;
    float gv = g_gate[idx];
    g_comb[idx] = gv * g_y[idx] + (1.0f - gv) * g_xt[idx];
}

// ---------------- launch ----------------
extern "C" void kernel_launch(void* const* d_in, const int* in_sizes, int n_in,
                              void* d_out, int out_size) {
    const float* x   = (const float*)d_in[0];
    const float* stu = (const float*)d_in[1];
    const float* Mi  = (const float*)d_in[2];
    const float* Mf  = (const float*)d_in[3];
    const float* Wq  = (const float*)d_in[4];
    const float* bq  = (const float*)d_in[5];
    const float* Wk  = (const float*)d_in[6];
    const float* bk  = (const float*)d_in[7];
    const float* Wv  = (const float*)d_in[8];
    const float* bv  = (const float*)d_in[9];
    const float* Wg  = (const float*)d_in[10];
    const float* bg  = (const float*)d_in[11];
    const float* Wo  = (const float*)d_in[12];
    const float* bo  = (const float*)d_in[13];
    const float* lnw = (const float*)d_in[14];
    const float* lnb = (const float*)d_in[15];
    float* out = (float*)d_out;

    float *p_uproj, *p_q, *p_k, *p_v, *p_gate, *p_comb;
    cudaGetSymbolAddress((void**)&p_uproj, g_uproj);
    cudaGetSymbolAddress((void**)&p_q,     g_q);
    cudaGetSymbolAddress((void**)&p_k,     g_k);
    cudaGetSymbolAddress((void**)&p_v,     g_v);
    cudaGetSymbolAddress((void**)&p_gate,  g_gate);
    cudaGetSymbolAddress((void**)&p_comb,  g_comb);

    const int M = BD * TT;  // 2048

    // 1. spectral filter projection
    phi_kernel<<<(T2 * DD + 255) / 256, 256>>>(stu, Mf);

    // 2. u_proj = x @ M_inputs
    dim3 ggrid(DD / 64, M / 128);
    gemm_kernel<false, 0><<<ggrid, 256>>>(x, Mi, nullptr, p_uproj, M, DD, DD);

    // 3. causal conv (parity split)
    conv_kernel<<<dim3(DD / 64, T2 / 64, BD * 2), dim3(64, 4)>>>();

    // 4. layernorm -> x_tilde
    ln_kernel<<<M, 128>>>(lnw, lnb);

    // 5. projections with activations
    gemm_kernel<true, 1><<<ggrid, 256>>>(x, Wq, bq, p_q,    M, DD, DD);
    gemm_kernel<true, 1><<<ggrid, 256>>>(x, Wk, bk, p_k,    M, DD, DD);
    gemm_kernel<true, 1><<<ggrid, 256>>>(x, Wv, bv, p_v,    M, DD, DD);
    gemm_kernel<true, 2><<<ggrid, 256>>>(x, Wg, bg, p_gate, M, DD, DD);

    // 6. chunked linear attention
    attn_state_kernel<<<dim3(NCH, NH, BD), 256>>>();
    attn_scan_kernel<<<256, 256>>>();
    static const int attn_smem = 5 * 64 * 65 * 4;
    cudaFuncSetAttribute(attn_out_kernel, cudaFuncAttributeMaxDynamicSharedMemorySize, attn_smem);
    attn_out_kernel<<<dim3(NCH, NH, BD), 256, attn_smem>>>();

    // 7. combine
    combine_kernel<<<(BD * TT * DD + 255) / 256, 256>>>();

    // 8. output projection
    gemm_kernel<true, 0><<<ggrid, 256>>>(p_comb, Wo, bo, out, M, DD, DD);
}

// round 2
// speedup vs baseline: 1.8006x; 1.8006x over previous
#include <cuda_runtime.h>
#include <math.h>
#include <stdint.h>

// Problem constants
#define BD   2
#define TT   1024
#define DD   512
#define NH   8
#define HDIM 64
#define CHK  64
#define NCH  16
#define T2   512   // half length (parity split)

// ---------------- scratch (device globals; no allocation allowed) ----------------
__device__ float g_vfilt[T2 * DD];
__device__ float g_uproj[BD * TT * DD];
__device__ float g_w[BD * TT * DD];
__device__ float g_xt[BD * TT * DD];
__device__ float g_q[BD * TT * DD];
__device__ float g_k[BD * TT * DD];
__device__ float g_v[BD * TT * DD];
__device__ float g_gate[BD * TT * DD];
__device__ float g_y[BD * TT * DD];
__device__ float g_comb[BD * TT * DD];
__device__ float g_state[BD * NH * NCH * HDIM * HDIM];
__device__ float g_miT[DD * DD];   // M_inputs transposed (N x K form)

// ---------------- activation helpers ----------------
__device__ __forceinline__ float gelu_tanh(float v) {
    float c = 0.7978845608028654f;
    float t = tanhf(c * (v + 0.044715f * v * v * v));
    return 0.5f * v * (1.0f + t);
}
__device__ __forceinline__ float sigm(float v) {
    return 1.0f / (1.0f + expf(-v));
}
__device__ __forceinline__ float apply_act(float v, int act) {
    if (act == 1) return gelu_tanh(v);
    if (act == 2) return sigm(v);
    return v;
}
__device__ __forceinline__ uint32_t f2tf(float v) {
    uint32_t o;
    asm("cvt.rna.tf32.f32 %0, %1;" : "=r"(o) : "f"(v));
    return o;
}

// ---------------- tf32 MMA GEMM body ----------------
// C[M,512] = act(A[M,512] @ B^T + bias), B is 512x512 row-major (N x K).
// Block tile 128x64, BK=32, 256 threads (8 warps as 4Mx2N, warp tile 32x32).
#define ASTR 36

__device__ __forceinline__ void mma_step(float* acc, const uint32_t* a, const uint32_t* b) {
    asm volatile(
        "mma.sync.aligned.m16n8k8.row.col.f32.tf32.tf32.f32 "
        "{%0,%1,%2,%3}, {%4,%5,%6,%7}, {%8,%9}, {%0,%1,%2,%3};"
        : "+f"(acc[0]), "+f"(acc[1]), "+f"(acc[2]), "+f"(acc[3])
        : "r"(a[0]), "r"(a[1]), "r"(a[2]), "r"(a[3]), "r"(b[0]), "r"(b[1]));
}

__device__ __forceinline__ void gemm_body(const float* __restrict__ A,
                                          const float* __restrict__ B,
                                          const float* __restrict__ bias,
                                          float* __restrict__ C, int act,
                                          uint32_t* As, uint32_t* Bs) {
    const int K = 512, NK = 16;
    int tx = threadIdx.x;
    int m0 = blockIdx.y * 128, n0 = blockIdx.x * 64;

    // ---- prologue: load tile kt=0 ----
    {
#pragma unroll
        for (int i = 0; i < 4; i++) {
            int c = tx + i * 256;
            int row = c >> 3, kc = (c & 7) << 2;
            float4 v = *(const float4*)&A[(size_t)(m0 + row) * K + kc];
            As[row * ASTR + kc + 0] = f2tf(v.x);
            As[row * ASTR + kc + 1] = f2tf(v.y);
            As[row * ASTR + kc + 2] = f2tf(v.z);
            As[row * ASTR + kc + 3] = f2tf(v.w);
        }
#pragma unroll
        for (int i = 0; i < 2; i++) {
            int c = tx + i * 256;
            int row = c >> 3, kc = (c & 7) << 2;
            float4 v = *(const float4*)&B[(size_t)(n0 + row) * K + kc];
            Bs[row * ASTR + kc + 0] = f2tf(v.x);
            Bs[row * ASTR + kc + 1] = f2tf(v.y);
            Bs[row * ASTR + kc + 2] = f2tf(v.z);
            Bs[row * ASTR + kc + 3] = f2tf(v.w);
        }
    }
    __syncthreads();

    int lane = tx & 31, w = tx >> 5;
    int wm = w >> 1, wn = w & 1;          // 4 x 2 warp grid
    int g = lane >> 2, tig = lane & 3;

    float acc[2][4][4];
#pragma unroll
    for (int mt = 0; mt < 2; mt++)
#pragma unroll
        for (int nt = 0; nt < 4; nt++)
#pragma unroll
            for (int j = 0; j < 4; j++) acc[mt][nt][j] = 0.f;

    for (int kt = 0; kt < NK; kt++) {
        float4 av[4], bv[2];
        if (kt < NK - 1) {
            int kg = (kt + 1) * 32;
#pragma unroll
            for (int i = 0; i < 4; i++) {
                int c = tx + i * 256;
                int row = c >> 3, kc = (c & 7) << 2;
                av[i] = *(const float4*)&A[(size_t)(m0 + row) * K + kg + kc];
            }
#pragma unroll
            for (int i = 0; i < 2; i++) {
                int c = tx + i * 256;
                int row = c >> 3, kc = (c & 7) << 2;
                bv[i] = *(const float4*)&B[(size_t)(n0 + row) * K + kg + kc];
            }
        }
        // ---- compute 4 k8 steps from smem ----
#pragma unroll
        for (int k8 = 0; k8 < 4; k8++) {
            int kb = k8 * 8;
            uint32_t af[2][4], bf[4][2];
#pragma unroll
            for (int mt = 0; mt < 2; mt++) {
                int base = (wm * 32 + mt * 16 + g) * ASTR + kb + tig;
                af[mt][0] = As[base];
                af[mt][1] = As[base + 8 * ASTR];
                af[mt][2] = As[base + 4];
                af[mt][3] = As[base + 8 * ASTR + 4];
            }
#pragma unroll
            for (int nt = 0; nt < 4; nt++) {
                int base = (wn * 32 + nt * 8 + g) * ASTR + kb + tig;
                bf[nt][0] = Bs[base];
                bf[nt][1] = Bs[base + 4];
            }
#pragma unroll
            for (int mt = 0; mt < 2; mt++)
#pragma unroll
                for (int nt = 0; nt < 4; nt++)
                    mma_step(acc[mt][nt], af[mt], bf[nt]);
        }
        if (kt < NK - 1) {
            __syncthreads();
#pragma unroll
            for (int i = 0; i < 4; i++) {
                int c = tx + i * 256;
                int row = c >> 3, kc = (c & 7) << 2;
                As[row * ASTR + kc + 0] = f2tf(av[i].x);
                As[row * ASTR + kc + 1] = f2tf(av[i].y);
                As[row * ASTR + kc + 2] = f2tf(av[i].z);
                As[row * ASTR + kc + 3] = f2tf(av[i].w);
            }
#pragma unroll
            for (int i = 0; i < 2; i++) {
                int c = tx + i * 256;
                int row = c >> 3, kc = (c & 7) << 2;
                Bs[row * ASTR + kc + 0] = f2tf(bv[i].x);
                Bs[row * ASTR + kc + 1] = f2tf(bv[i].y);
                Bs[row * ASTR + kc + 2] = f2tf(bv[i].z);
                Bs[row * ASTR + kc + 3] = f2tf(bv[i].w);
            }
            __syncthreads();
        }
    }

    // ---- epilogue ----
#pragma unroll
    for (int mt = 0; mt < 2; mt++) {
#pragma unroll
        for (int nt = 0; nt < 4; nt++) {
            int row = m0 + wm * 32 + mt * 16 + g;
            int col = n0 + wn * 32 + nt * 8 + 2 * tig;
            float bb0 = bias ? bias[col] : 0.f;
            float bb1 = bias ? bias[col + 1] : 0.f;
            float2 o0, o1;
            o0.x = apply_act(acc[mt][nt][0] + bb0, act);
            o0.y = apply_act(acc[mt][nt][1] + bb1, act);
            o1.x = apply_act(acc[mt][nt][2] + bb0, act);
            o1.y = apply_act(acc[mt][nt][3] + bb1, act);
            *(float2*)&C[(size_t)row * 512 + col] = o0;
            *(float2*)&C[(size_t)(row + 8) * 512 + col] = o1;
        }
    }
}

__global__ __launch_bounds__(256) void gemm_tf32_kernel(
    const float* __restrict__ A, const float* __restrict__ B,
    const float* __restrict__ bias, float* __restrict__ C, int act) {
    __shared__ uint32_t As[128 * ASTR];
    __shared__ uint32_t Bs[64 * ASTR];
    gemm_body(A, B, bias, C, act, As, Bs);
}

// Fused QKV+gate: grid.z selects weight/output; all share A = x.
__global__ __launch_bounds__(256) void qkvg_kernel(
    const float* __restrict__ x,
    const float* __restrict__ Wq, const float* __restrict__ Wk,
    const float* __restrict__ Wv, const float* __restrict__ Wg,
    const float* __restrict__ bq, const float* __restrict__ bk,
    const float* __restrict__ bv, const float* __restrict__ bg,
    float* __restrict__ oq, float* __restrict__ ok,
    float* __restrict__ ov, float* __restrict__ og) {
    __shared__ uint32_t As[128 * ASTR];
    __shared__ uint32_t Bs[64 * ASTR];
    int z = blockIdx.z;
    const float* W = (z == 0) ? Wq : (z == 1) ? Wk : (z == 2) ? Wv : Wg;
    const float* b = (z == 0) ? bq : (z == 1) ? bk : (z == 2) ? bv : bg;
    float* o = (z == 0) ? oq : (z == 1) ? ok : (z == 2) ? ov : og;
    int act = (z == 3) ? 2 : 1;
    gemm_body(x, W, b, o, act, As, Bs);
}

// ---------------- transpose M_inputs (512x512) ----------------
__global__ void transpose_kernel(const float* __restrict__ in) {
    __shared__ float t[32][33];
    int bx = blockIdx.x * 32, by = blockIdx.y * 32;
    int tx = threadIdx.x, ty = threadIdx.y;
    for (int i = ty; i < 32; i += 8)
        t[i][tx] = in[(size_t)(by + i) * DD + bx + tx];
    __syncthreads();
    for (int i = ty; i < 32; i += 8)
        g_miT[(size_t)(bx + i) * DD + by + tx] = t[tx][i];
}

// ---------------- phi kernel: Vfilt[s2][r] = 2 * sum_k sf[2*s2,k]*Mf[k,r] ----------------
__global__ void phi_kernel(const float* __restrict__ sf, const float* __restrict__ mf) {
    int idx = blockIdx.x * blockDim.x + threadIdx.x;
    if (idx >= T2 * DD) return;
    int s2 = idx >> 9;
    int r  = idx & 511;
    const float* srow = sf + (size_t)(2 * s2) * 24;
    float acc = 0.f;
#pragma unroll
    for (int k = 0; k < 24; k++) acc += srow[k] * mf[k * DD + r];
    g_vfilt[idx] = 2.0f * acc;
}

// ---------------- conv kernel (parity-split causal conv, length 512) ----------------
__global__ void conv_kernel() {
    __shared__ float us[64][64];
    __shared__ float vs[128][64];
    int rx = threadIdx.x;
    int ty = threadIdx.y;
    int r0  = blockIdx.x * 64;
    int tt0 = blockIdx.y * 64;
    int bz  = blockIdx.z;
    int b = bz >> 1, p = bz & 1;
    float acc[16];
#pragma unroll
    for (int i = 0; i < 16; i++) acc[i] = 0.f;
    const float* ub = g_uproj + (size_t)b * TT * DD;

    for (int j0 = 0; j0 <= tt0; j0 += 64) {
        for (int jj = ty; jj < 64; jj += 4)
            us[jj][rx] = ub[(size_t)(2 * (j0 + jj) + p) * DD + r0 + rx];
        int lagbase = tt0 - j0 - 63;
        for (int l = ty; l < 128; l += 4) {
            int lag = lagbase + l;
            vs[l][rx] = (lag >= 0 && lag < T2) ? g_vfilt[(size_t)lag * DD + r0 + rx] : 0.f;
        }
        __syncthreads();
#pragma unroll 4
        for (int jj = 0; jj < 64; jj++) {
            float uv = us[jj][rx];
            int base = ty * 16 + 63 - jj;
#pragma unroll
            for (int i = 0; i < 16; i++)
                acc[i] += vs[base + i][rx] * uv;
        }
        __syncthreads();
    }
#pragma unroll
    for (int i = 0; i < 16; i++) {
        int tt = tt0 + ty * 16 + i;
        g_w[((size_t)b * TT + 2 * tt + p) * DD + r0 + rx] = acc[i];
    }
}

// ---------------- layernorm over last dim (512) ----------------
__global__ void ln_kernel(const float* __restrict__ lw, const float* __restrict__ lb) {
    int row = blockIdx.x;
    const float* x = g_w + (size_t)row * DD;
    float* o = g_xt + (size_t)row * DD;
    int tx = threadIdx.x;
    float4 v = *(const float4*)&x[tx * 4];
    float s  = v.x + v.y + v.z + v.w;
    float ss = v.x * v.x + v.y * v.y + v.z * v.z + v.w * v.w;
#pragma unroll
    for (int off = 16; off; off >>= 1) {
        s  += __shfl_xor_sync(0xffffffffu, s,  off);
        ss += __shfl_xor_sync(0xffffffffu, ss, off);
    }
    __shared__ float rs[4], rss[4];
    if ((tx & 31) == 0) { rs[tx >> 5] = s; rss[tx >> 5] = ss; }
    __syncthreads();
    float tot  = rs[0] + rs[1] + rs[2] + rs[3];
    float tots = rss[0] + rss[1] + rss[2] + rss[3];
    float mu  = tot * (1.0f / DD);
    float var = tots * (1.0f / DD) - mu * mu;
    float inv = rsqrtf(var + 1e-5f);
    float4 w4 = *(const float4*)&lw[tx * 4];
    float4 b4 = *(const float4*)&lb[tx * 4];
    float4 out;
    out.x = (v.x - mu) * inv * w4.x + b4.x;
    out.y = (v.y - mu) * inv * w4.y + b4.y;
    out.z = (v.z - mu) * inv * w4.z + b4.z;
    out.w = (v.w - mu) * inv * w4.w + b4.w;
    *(float4*)&o[tx * 4] = out;
}

// ---------------- attention: per-chunk local KV state ----------------
__global__ void attn_state_kernel() {
    __shared__ float Vs[64][65];
    __shared__ float Ks[64][65];
    int c = blockIdx.x, h = blockIdx.y, b = blockIdx.z;
    const float* Vp = g_v + ((size_t)b * TT + c * CHK) * DD + h * HDIM;
    const float* Kp = g_k + ((size_t)b * TT + c * CHK) * DD + h * HDIM;
    int tx = threadIdx.x;
    for (int idx = tx; idx < 4096; idx += 256) {
        int s = idx >> 6, q = idx & 63;
        Vs[s][q] = Vp[(size_t)s * DD + q];
        Ks[s][q] = Kp[(size_t)s * DD + q];
    }
    __syncthreads();
    int tn = tx & 15, tm = tx >> 4;
    float acc[4][4];
#pragma unroll
    for (int i = 0; i < 4; i++)
#pragma unroll
        for (int j = 0; j < 4; j++) acc[i][j] = 0.f;
    for (int s = 0; s < 64; s++) {
        float a[4], bb[4];
#pragma unroll
        for (int i = 0; i < 4; i++) a[i] = Vs[s][tm * 4 + i];
#pragma unroll
        for (int j = 0; j < 4; j++) bb[j] = Ks[s][tn * 4 + j];
#pragma unroll
        for (int i = 0; i < 4; i++)
#pragma unroll
            for (int j = 0; j < 4; j++) acc[i][j] += a[i] * bb[j];
    }
    float* Lp = g_state + (((size_t)(b * NH + h) * NCH + c) * (HDIM * HDIM));
#pragma unroll
    for (int i = 0; i < 4; i++)
#pragma unroll
        for (int j = 0; j < 4; j++)
            Lp[(tm * 4 + i) * HDIM + tn * 4 + j] = acc[i][j];
}

// ---------------- attention: exclusive prefix over chunks ----------------
__global__ void attn_scan_kernel() {
    int idx = blockIdx.x * blockDim.x + threadIdx.x;
    int bh = idx >> 12, e = idx & 4095;
    float* base = g_state + (size_t)bh * NCH * 4096 + e;
    float run = 0.f;
#pragma unroll
    for (int c = 0; c < NCH; c++) {
        float v = base[(size_t)c * 4096];
        base[(size_t)c * 4096] = run;
        run += v;
    }
}

// ---------------- attention: per-chunk output ----------------
__global__ void attn_out_kernel() {
    extern __shared__ float sm[];
    float* Qs = sm;
    float* Vs = sm + 64 * 65;
    float* Ks = sm + 2 * 64 * 65;
    float* Hs = sm + 3 * 64 * 65;
    float* Ss = sm + 4 * 64 * 65;
    int c = blockIdx.x, h = blockIdx.y, b = blockIdx.z;
    int tx = threadIdx.x;
    const float* Qp = g_q + ((size_t)b * TT + c * CHK) * DD + h * HDIM;
    const float* Kp = g_k + ((size_t)b * TT + c * CHK) * DD + h * HDIM;
    const float* Vp = g_v + ((size_t)b * TT + c * CHK) * DD + h * HDIM;
    const float* Hp = g_state + (((size_t)(b * NH + h) * NCH + c) * 4096);
    for (int idx = tx; idx < 4096; idx += 256) {
        int s = idx >> 6, q = idx & 63;
        Qs[s * 65 + q] = Qp[(size_t)s * DD + q];
        Ks[s * 65 + q] = Kp[(size_t)s * DD + q];
        Vs[s * 65 + q] = Vp[(size_t)s * DD + q];
        Hs[s * 65 + q] = Hp[idx];
    }
    __syncthreads();
    int tn = tx & 15, tm = tx >> 4;
    {
        float acc[4][4];
#pragma unroll
        for (int i = 0; i < 4; i++)
#pragma unroll
            for (int j = 0; j < 4; j++) acc[i][j] = 0.f;
        for (int n = 0; n < 64; n++) {
            float a[4], bb[4];
#pragma unroll
            for (int i = 0; i < 4; i++) a[i] = Qs[(tm * 4 + i) * 65 + n];
#pragma unroll
            for (int j = 0; j < 4; j++) bb[j] = Vs[(tn * 4 + j) * 65 + n];
#pragma unroll
            for (int i = 0; i < 4; i++)
#pragma unroll
                for (int j = 0; j < 4; j++) acc[i][j] += a[i] * bb[j];
        }
#pragma unroll
        for (int i = 0; i < 4; i++)
#pragma unroll
            for (int j = 0; j < 4; j++) {
                int row = tm * 4 + i, col = tn * 4 + j;
                Ss[row * 65 + col] = (col <= row) ? acc[i][j] : 0.f;
            }
    }
    __syncthreads();
    float acc[4][4];
#pragma unroll
    for (int i = 0; i < 4; i++)
#pragma unroll
        for (int j = 0; j < 4; j++) acc[i][j] = 0.f;
    for (int jx = 0; jx < 64; jx++) {
        float a[4], bb[4];
#pragma unroll
        for (int i = 0; i < 4; i++) a[i] = Ss[(tm * 4 + i) * 65 + jx];
#pragma unroll
        for (int j = 0; j < 4; j++) bb[j] = Ks[jx * 65 + tn * 4 + j];
#pragma unroll
        for (int i = 0; i < 4; i++)
#pragma unroll
            for (int j = 0; j < 4; j++) acc[i][j] += a[i] * bb[j];
    }
    for (int px = 0; px < 64; px++) {
        float a[4], bb[4];
#pragma unroll
        for (int i = 0; i < 4; i++) a[i] = Qs[(tm * 4 + i) * 65 + px];
#pragma unroll
        for (int j = 0; j < 4; j++) bb[j] = Hs[px * 65 + tn * 4 + j];
#pragma unroll
        for (int i = 0; i < 4; i++)
#pragma unroll
            for (int j = 0; j < 4; j++) acc[i][j] += a[i] * bb[j];
    }
#pragma unroll
    for (int i = 0; i < 4; i++) {
        int t = c * CHK + tm * 4 + i;
#pragma unroll
        for (int j = 0; j < 4; j++)
            g_y[((size_t)b * TT + t) * DD + h * HDIM + tn * 4 + j] = acc[i][j];
    }
}

// ---------------- combine ----------------
__global__ void combine_kernel() {
    int idx = blockIdx.x * blockDim.x + threadIdx.x;
    if (idx >= BD * TT * DD) return;
    float gv = g_gate[idx];
    g_comb[idx] = gv * g_y[idx] + (1.0f - gv) * g_xt[idx];
}

// ---------------- launch ----------------
extern "C" void kernel_launch(void* const* d_in, const int* in_sizes, int n_in,
                              void* d_out, int out_size) {
    const float* x   = (const float*)d_in[0];
    const float* stu = (const float*)d_in[1];
    const float* Mi  = (const float*)d_in[2];
    const float* Mf  = (const float*)d_in[3];
    const float* Wq  = (const float*)d_in[4];
    const float* bq  = (const float*)d_in[5];
    const float* Wk  = (const float*)d_in[6];
    const float* bk  = (const float*)d_in[7];
    const float* Wv  = (const float*)d_in[8];
    const float* bv  = (const float*)d_in[9];
    const float* Wg  = (const float*)d_in[10];
    const float* bg  = (const float*)d_in[11];
    const float* Wo  = (const float*)d_in[12];
    const float* bo  = (const float*)d_in[13];
    const float* lnw = (const float*)d_in[14];
    const float* lnb = (const float*)d_in[15];
    float* out = (float*)d_out;

    float *p_uproj, *p_q, *p_k, *p_v, *p_gate, *p_comb, *p_miT;
    cudaGetSymbolAddress((void**)&p_uproj, g_uproj);
    cudaGetSymbolAddress((void**)&p_q,     g_q);
    cudaGetSymbolAddress((void**)&p_k,     g_k);
    cudaGetSymbolAddress((void**)&p_v,     g_v);
    cudaGetSymbolAddress((void**)&p_gate,  g_gate);
    cudaGetSymbolAddress((void**)&p_comb,  g_comb);
    cudaGetSymbolAddress((void**)&p_miT,   g_miT);

    const int M = BD * TT;  // 2048
    dim3 ggrid(DD / 64, M / 128);

    // 1. spectral filter projection + Mi transpose
    phi_kernel<<<(T2 * DD + 255) / 256, 256>>>(stu, Mf);
    transpose_kernel<<<dim3(16, 16), dim3(32, 8)>>>(Mi);

    // 2. u_proj = x @ Mi  (= x @ MiT^T)
    gemm_tf32_kernel<<<ggrid, 256>>>(x, p_miT, nullptr, p_uproj, 0);

    // 3. causal conv (parity split)
    conv_kernel<<<dim3(DD / 64, T2 / 64, BD * 2), dim3(64, 4)>>>();

    // 4. layernorm -> x_tilde
    ln_kernel<<<M, 128>>>(lnw, lnb);

    // 5. fused Q/K/V/gate projections
    qkvg_kernel<<<dim3(DD / 64, M / 128, 4), 256>>>(
        x, Wq, Wk, Wv, Wg, bq, bk, bv, bg, p_q, p_k, p_v, p_gate);

    // 6. chunked linear attention
    attn_state_kernel<<<dim3(NCH, NH, BD), 256>>>();
    attn_scan_kernel<<<256, 256>>>();
    static const int attn_smem = 5 * 64 * 65 * 4;
    cudaFuncSetAttribute(attn_out_kernel, cudaFuncAttributeMaxDynamicSharedMemorySize, attn_smem);
    attn_out_kernel<<<dim3(NCH, NH, BD), 256, attn_smem>>>();

    // 7. combine
    combine_kernel<<<(BD * TT * DD + 255) / 256, 256>>>();

    // 8. output projection
    gemm_tf32_kernel<<<ggrid, 256>>>(p_comb, Wo, bo, out, 0);
}

// round 8
// speedup vs baseline: 2.1350x; 1.1857x over previous
#include <cuda_runtime.h>
#include <math.h>
#include <stdint.h>

// Problem constants
#define BD   2
#define TT   1024
#define DD   512
#define NH   8
#define HDIM 64
#define CHK  64
#define NCH  16
#define T2   512   // half length (parity split)

// ---------------- scratch ----------------
__device__ float g_vfilt[T2 * DD];
__device__ float g_uproj[BD * TT * DD];
__device__ float g_w[BD * TT * DD];
__device__ float g_xt[BD * TT * DD];
__device__ float g_q[BD * TT * DD];
__device__ float g_k[BD * TT * DD];
__device__ float g_v[BD * TT * DD];
__device__ float g_gate[BD * TT * DD];
__device__ float g_comb[BD * TT * DD];
__device__ float g_state[BD * NH * NCH * HDIM * HDIM];
__device__ float g_miT[DD * DD];

// ---------------- helpers ----------------
__device__ __forceinline__ float gelu_tanh(float v) {
    float c = 0.7978845608028654f;
    float t = tanhf(c * (v + 0.044715f * v * v * v));
    return 0.5f * v * (1.0f + t);
}
__device__ __forceinline__ float sigm(float v) {
    return 1.0f / (1.0f + expf(-v));
}
__device__ __forceinline__ float apply_act(float v, int act) {
    if (act == 1) return gelu_tanh(v);
    if (act == 2) return sigm(v);
    return v;
}
__device__ __forceinline__ uint32_t f2tf(float v) {
    uint32_t o;
    asm("cvt.rna.tf32.f32 %0, %1;" : "=r"(o) : "f"(v));
    return o;
}

// ---------------- tf32 MMA GEMM body (A MxK rm, B NxK rm => C = act(A B^T + bias)) ----------------
#define ASTR 36

__device__ __forceinline__ void mma_step(float* acc, const uint32_t* a, const uint32_t* b) {
    asm volatile(
        "mma.sync.aligned.m16n8k8.row.col.f32.tf32.tf32.f32 "
        "{%0,%1,%2,%3}, {%4,%5,%6,%7}, {%8,%9}, {%0,%1,%2,%3};"
        : "+f"(acc[0]), "+f"(acc[1]), "+f"(acc[2]), "+f"(acc[3])
        : "r"(a[0]), "r"(a[1]), "r"(a[2]), "r"(a[3]), "r"(b[0]), "r"(b[1]));
}

__device__ __forceinline__ void gemm_body(const float* __restrict__ A,
                                          const float* __restrict__ B,
                                          const float* __restrict__ bias,
                                          float* __restrict__ C, int act,
                                          uint32_t* As, uint32_t* Bs) {
    const int K = 512, NK = 16;
    int tx = threadIdx.x;
    int m0 = blockIdx.y * 128, n0 = blockIdx.x * 64;

    {
#pragma unroll
        for (int i = 0; i < 4; i++) {
            int c = tx + i * 256;
            int row = c >> 3, kc = (c & 7) << 2;
            float4 v = *(const float4*)&A[(size_t)(m0 + row) * K + kc];
            As[row * ASTR + kc + 0] = f2tf(v.x);
            As[row * ASTR + kc + 1] = f2tf(v.y);
            As[row * ASTR + kc + 2] = f2tf(v.z);
            As[row * ASTR + kc + 3] = f2tf(v.w);
        }
#pragma unroll
        for (int i = 0; i < 2; i++) {
            int c = tx + i * 256;
            int row = c >> 3, kc = (c & 7) << 2;
            float4 v = *(const float4*)&B[(size_t)(n0 + row) * K + kc];
            Bs[row * ASTR + kc + 0] = f2tf(v.x);
            Bs[row * ASTR + kc + 1] = f2tf(v.y);
            Bs[row * ASTR + kc + 2] = f2tf(v.z);
            Bs[row * ASTR + kc + 3] = f2tf(v.w);
        }
    }
    __syncthreads();

    int lane = tx & 31, w = tx >> 5;
    int wm = w >> 1, wn = w & 1;
    int g = lane >> 2, tig = lane & 3;

    float acc[2][4][4];
#pragma unroll
    for (int mt = 0; mt < 2; mt++)
#pragma unroll
        for (int nt = 0; nt < 4; nt++)
#pragma unroll
            for (int j = 0; j < 4; j++) acc[mt][nt][j] = 0.f;

    for (int kt = 0; kt < NK; kt++) {
        float4 av[4], bv[2];
        if (kt < NK - 1) {
            int kg = (kt + 1) * 32;
#pragma unroll
            for (int i = 0; i < 4; i++) {
                int c = tx + i * 256;
                int row = c >> 3, kc = (c & 7) << 2;
                av[i] = *(const float4*)&A[(size_t)(m0 + row) * K + kg + kc];
            }
#pragma unroll
            for (int i = 0; i < 2; i++) {
                int c = tx + i * 256;
                int row = c >> 3, kc = (c & 7) << 2;
                bv[i] = *(const float4*)&B[(size_t)(n0 + row) * K + kg + kc];
            }
        }
#pragma unroll
        for (int k8 = 0; k8 < 4; k8++) {
            int kb = k8 * 8;
            uint32_t af[2][4], bf[4][2];
#pragma unroll
            for (int mt = 0; mt < 2; mt++) {
                int base = (wm * 32 + mt * 16 + g) * ASTR + kb + tig;
                af[mt][0] = As[base];
                af[mt][1] = As[base + 8 * ASTR];
                af[mt][2] = As[base + 4];
                af[mt][3] = As[base + 8 * ASTR + 4];
            }
#pragma unroll
            for (int nt = 0; nt < 4; nt++) {
                int base = (wn * 32 + nt * 8 + g) * ASTR + kb + tig;
                bf[nt][0] = Bs[base];
                bf[nt][1] = Bs[base + 4];
            }
#pragma unroll
            for (int mt = 0; mt < 2; mt++)
#pragma unroll
                for (int nt = 0; nt < 4; nt++)
                    mma_step(acc[mt][nt], af[mt], bf[nt]);
        }
        if (kt < NK - 1) {
            __syncthreads();
#pragma unroll
            for (int i = 0; i < 4; i++) {
                int c = tx + i * 256;
                int row = c >> 3, kc = (c & 7) << 2;
                As[row * ASTR + kc + 0] = f2tf(av[i].x);
                As[row * ASTR + kc + 1] = f2tf(av[i].y);
                As[row * ASTR + kc + 2] = f2tf(av[i].z);
                As[row * ASTR + kc + 3] = f2tf(av[i].w);
            }
#pragma unroll
            for (int i = 0; i < 2; i++) {
                int c = tx + i * 256;
                int row = c >> 3, kc = (c & 7) << 2;
                Bs[row * ASTR + kc + 0] = f2tf(bv[i].x);
                Bs[row * ASTR + kc + 1] = f2tf(bv[i].y);
                Bs[row * ASTR + kc + 2] = f2tf(bv[i].z);
                Bs[row * ASTR + kc + 3] = f2tf(bv[i].w);
            }
            __syncthreads();
        }
    }

#pragma unroll
    for (int mt = 0; mt < 2; mt++) {
#pragma unroll
        for (int nt = 0; nt < 4; nt++) {
            int row = m0 + wm * 32 + mt * 16 + g;
            int col = n0 + wn * 32 + nt * 8 + 2 * tig;
            float bb0 = bias ? bias[col] : 0.f;
            float bb1 = bias ? bias[col + 1] : 0.f;
            float2 o0, o1;
            o0.x = apply_act(acc[mt][nt][0] + bb0, act);
            o0.y = apply_act(acc[mt][nt][1] + bb1, act);
            o1.x = apply_act(acc[mt][nt][2] + bb0, act);
            o1.y = apply_act(acc[mt][nt][3] + bb1, act);
            *(float2*)&C[(size_t)row * 512 + col] = o0;
            *(float2*)&C[(size_t)(row + 8) * 512 + col] = o1;
        }
    }
}

__global__ __launch_bounds__(256) void gemm_tf32_kernel(
    const float* __restrict__ A, const float* __restrict__ B,
    const float* __restrict__ bias, float* __restrict__ C, int act) {
    __shared__ uint32_t As[128 * ASTR];
    __shared__ uint32_t Bs[64 * ASTR];
    gemm_body(A, B, bias, C, act, As, Bs);
}

// All 5 input projections (uproj + Q,K,V,gate) in one launch
__global__ __launch_bounds__(256) void proj_kernel(
    const float* __restrict__ x,
    const float* __restrict__ Wq, const float* __restrict__ Wk,
    const float* __restrict__ Wv, const float* __restrict__ Wg,
    const float* __restrict__ bq, const float* __restrict__ bk,
    const float* __restrict__ bv, const float* __restrict__ bg,
    float* __restrict__ oq, float* __restrict__ ok,
    float* __restrict__ ov, float* __restrict__ og) {
    __shared__ uint32_t As[128 * ASTR];
    __shared__ uint32_t Bs[64 * ASTR];
    int z = blockIdx.z;
    const float* W;
    const float* b;
    float* o;
    int act;
    if (z == 0) {
        float* miT; asm("cvta.global.u64 %0, g_miT;" : "=l"(miT));
        W = miT; b = nullptr;
        float* up; asm("cvta.global.u64 %0, g_uproj;" : "=l"(up));
        o = up; act = 0;
    } else if (z == 1) { W = Wq; b = bq; o = oq; act = 1; }
    else if (z == 2)   { W = Wk; b = bk; o = ok; act = 1; }
    else if (z == 3)   { W = Wv; b = bv; o = ov; act = 1; }
    else               { W = Wg; b = bg; o = og; act = 2; }
    gemm_body(x, W, b, o, act, As, Bs);
}

// ---------------- transpose M_inputs ----------------
__global__ void transpose_kernel(const float* __restrict__ in) {
    __shared__ float t[32][33];
    int bx = blockIdx.x * 32, by = blockIdx.y * 32;
    int tx = threadIdx.x, ty = threadIdx.y;
    for (int i = ty; i < 32; i += 8)
        t[i][tx] = in[(size_t)(by + i) * DD + bx + tx];
    __syncthreads();
    for (int i = ty; i < 32; i += 8)
        g_miT[(size_t)(bx + i) * DD + by + tx] = t[tx][i];
}

// ---------------- phi kernel ----------------
__global__ void phi_kernel(const float* __restrict__ sf, const float* __restrict__ mf) {
    int idx = blockIdx.x * blockDim.x + threadIdx.x;
    if (idx >= T2 * DD) return;
    int s2 = idx >> 9;
    int r  = idx & 511;
    const float* srow = sf + (size_t)(2 * s2) * 24;
    float acc = 0.f;
#pragma unroll
    for (int k = 0; k < 24; k++) acc += srow[k] * mf[k * DD + r];
    g_vfilt[idx] = 2.0f * acc;
}

// ---------------- conv kernel: sliding-window register reuse ----------------
// w_p[b,tt,r] = sum_{j<=tt} Vfilt[tt-j, r] * u[b, 2j+p, r];  output row 2*tt+p.
__global__ __launch_bounds__(256) void conv_kernel() {
    __shared__ float us[64][64];    // u tile
    __shared__ float vs[128][64];   // filter tile (lag window)
    int rx = threadIdx.x;           // 0..63
    int ty = threadIdx.y;           // 0..3
    int tid = ty * 64 + rx;
    int r0  = blockIdx.x * 64;
    int tt0 = (gridDim.y - 1 - blockIdx.y) * 64;   // heaviest blocks launch first
    int bz  = blockIdx.z;
    int b = bz >> 1, p = bz & 1;
    float acc[16];
#pragma unroll
    for (int i = 0; i < 16; i++) acc[i] = 0.f;
    const float* ub = g_uproj + (size_t)b * TT * DD;
    const int base = ty * 16 + 63;

    for (int j0 = 0; j0 <= tt0; j0 += 64) {
        // us: 64x64 via float4 (4 per thread)
#pragma unroll
        for (int l = 0; l < 4; l++) {
            int idx = tid + l * 256;
            int row = idx >> 4, c4 = (idx & 15) * 4;
            *(float4*)&us[row][c4] =
                *(const float4*)&ub[(size_t)(2 * (j0 + row) + p) * DD + r0 + c4];
        }
        // vs: 128x64 lag rows [tt0-j0-63 .. tt0-j0+64] via float4 (8 per thread)
        int lagbase = tt0 - j0 - 63;
#pragma unroll
        for (int l = 0; l < 8; l++) {
            int idx = tid + l * 256;
            int row = idx >> 4, c4 = (idx & 15) * 4;
            int lag = lagbase + row;
            float4 v = (lag >= 0 && lag < T2)
                ? *(const float4*)&g_vfilt[(size_t)lag * DD + r0 + c4]
                : make_float4(0.f, 0.f, 0.f, 0.f);
            *(float4*)&vs[row][c4] = v;
        }
        __syncthreads();

        // sliding window: vwin[i] holds vs[base - jj + i][rx]
        float vwin[16];
#pragma unroll
        for (int wi = 0; wi < 16; wi++) vwin[wi] = vs[base + wi][rx];
#pragma unroll 16
        for (int jj = 0; jj < 64; jj++) {
            float uv = us[jj][rx];
#pragma unroll
            for (int i = 0; i < 16; i++) acc[i] += vwin[i] * uv;
            float nv = (jj < 63) ? vs[base - jj - 1][rx] : 0.f;
#pragma unroll
            for (int wi = 15; wi > 0; wi--) vwin[wi] = vwin[wi - 1];
            vwin[0] = nv;
        }
        __syncthreads();
    }
#pragma unroll
    for (int i = 0; i < 16; i++) {
        int tt = tt0 + ty * 16 + i;
        g_w[((size_t)b * TT + 2 * tt + p) * DD + r0 + rx] = acc[i];
    }
}

// ---------------- layernorm ----------------
__global__ void ln_kernel(const float* __restrict__ lw, const float* __restrict__ lb) {
    int row = blockIdx.x;
    const float* x = g_w + (size_t)row * DD;
    float* o = g_xt + (size_t)row * DD;
    int tx = threadIdx.x;
    float4 v = *(const float4*)&x[tx * 4];
    float s  = v.x + v.y + v.z + v.w;
    float ss = v.x * v.x + v.y * v.y + v.z * v.z + v.w * v.w;
#pragma unroll
    for (int off = 16; off; off >>= 1) {
        s  += __shfl_xor_sync(0xffffffffu, s,  off);
        ss += __shfl_xor_sync(0xffffffffu, ss, off);
    }
    __shared__ float rs[4], rss[4];
    if ((tx & 31) == 0) { rs[tx >> 5] = s; rss[tx >> 5] = ss; }
    __syncthreads();
    float tot  = rs[0] + rs[1] + rs[2] + rs[3];
    float tots = rss[0] + rss[1] + rss[2] + rss[3];
    float mu  = tot * (1.0f / DD);
    float var = tots * (1.0f / DD) - mu * mu;
    float inv = rsqrtf(var + 1e-5f);
    float4 w4 = *(const float4*)&lw[tx * 4];
    float4 b4 = *(const float4*)&lb[tx * 4];
    float4 out;
    out.x = (v.x - mu) * inv * w4.x + b4.x;
    out.y = (v.y - mu) * inv * w4.y + b4.y;
    out.z = (v.z - mu) * inv * w4.z + b4.z;
    out.w = (v.w - mu) * inv * w4.w + b4.w;
    *(float4*)&o[tx * 4] = out;
}

// ---------------- attention: per-chunk local KV state ----------------
__global__ void attn_state_kernel() {
    __shared__ float Vs[64][65];
    __shared__ float Ks[64][65];
    int c = blockIdx.x, h = blockIdx.y, b = blockIdx.z;
    const float* Vp = g_v + ((size_t)b * TT + c * CHK) * DD + h * HDIM;
    const float* Kp = g_k + ((size_t)b * TT + c * CHK) * DD + h * HDIM;
    int tx = threadIdx.x;
    for (int idx = tx; idx < 4096; idx += 256) {
        int s = idx >> 6, q = idx & 63;
        Vs[s][q] = Vp[(size_t)s * DD + q];
        Ks[s][q] = Kp[(size_t)s * DD + q];
    }
    __syncthreads();
    int tn = tx & 15, tm = tx >> 4;
    float acc[4][4];
#pragma unroll
    for (int i = 0; i < 4; i++)
#pragma unroll
        for (int j = 0; j < 4; j++) acc[i][j] = 0.f;
    for (int s = 0; s < 64; s++) {
        float a[4], bb[4];
#pragma unroll
        for (int i = 0; i < 4; i++) a[i] = Vs[s][tm * 4 + i];
#pragma unroll
        for (int j = 0; j < 4; j++) bb[j] = Ks[s][tn * 4 + j];
#pragma unroll
        for (int i = 0; i < 4; i++)
#pragma unroll
            for (int j = 0; j < 4; j++) acc[i][j] += a[i] * bb[j];
    }
    float* Lp = g_state + (((size_t)(b * NH + h) * NCH + c) * (HDIM * HDIM));
#pragma unroll
    for (int i = 0; i < 4; i++)
#pragma unroll
        for (int j = 0; j < 4; j++)
            Lp[(tm * 4 + i) * HDIM + tn * 4 + j] = acc[i][j];
}

// ---------------- attention: exclusive prefix over chunks ----------------
__global__ void attn_scan_kernel() {
    int idx = blockIdx.x * blockDim.x + threadIdx.x;
    int bh = idx >> 12, e = idx & 4095;
    float* base = g_state + (size_t)bh * NCH * 4096 + e;
    float run = 0.f;
#pragma unroll
    for (int c = 0; c < NCH; c++) {
        float v = base[(size_t)c * 4096];
        base[(size_t)c * 4096] = run;
        run += v;
    }
}

// ---------------- attention output + combine fused ----------------
// comb = gate * (Q_c Hprev + tril(Q_c V_c^T) K_c) + (1-gate) * x_tilde
__global__ void attn_out_kernel() {
    extern __shared__ float sm[];
    float* Qs = sm;
    float* Vs = sm + 64 * 65;
    float* Ks = sm + 2 * 64 * 65;
    float* Hs = sm + 3 * 64 * 65;
    float* Ss = sm + 4 * 64 * 65;
    int c = blockIdx.x, h = blockIdx.y, b = blockIdx.z;
    int tx = threadIdx.x;
    size_t rowbase = ((size_t)b * TT + c * CHK) * DD + h * HDIM;
    const float* Qp = g_q + rowbase;
    const float* Kp = g_k + rowbase;
    const float* Vp = g_v + rowbase;
    const float* Hp = g_state + (((size_t)(b * NH + h) * NCH + c) * 4096);
    for (int idx = tx; idx < 4096; idx += 256) {
        int s = idx >> 6, q = idx & 63;
        Qs[s * 65 + q] = Qp[(size_t)s * DD + q];
        Ks[s * 65 + q] = Kp[(size_t)s * DD + q];
        Vs[s * 65 + q] = Vp[(size_t)s * DD + q];
        Hs[s * 65 + q] = Hp[idx];
    }
    __syncthreads();
    int tn = tx & 15, tm = tx >> 4;
    {
        float acc[4][4];
#pragma unroll
        for (int i = 0; i < 4; i++)
#pragma unroll
            for (int j = 0; j < 4; j++) acc[i][j] = 0.f;
        for (int n = 0; n < 64; n++) {
            float a[4], bb[4];
#pragma unroll
            for (int i = 0; i < 4; i++) a[i] = Qs[(tm * 4 + i) * 65 + n];
#pragma unroll
            for (int j = 0; j < 4; j++) bb[j] = Vs[(tn * 4 + j) * 65 + n];
#pragma unroll
            for (int i = 0; i < 4; i++)
#pragma unroll
                for (int j = 0; j < 4; j++) acc[i][j] += a[i] * bb[j];
        }
#pragma unroll
        for (int i = 0; i < 4; i++)
#pragma unroll
            for (int j = 0; j < 4; j++) {
                int row = tm * 4 + i, col = tn * 4 + j;
                Ss[row * 65 + col] = (col <= row) ? acc[i][j] : 0.f;
            }
    }
    __syncthreads();
    float acc[4][4];
#pragma unroll
    for (int i = 0; i < 4; i++)
#pragma unroll
        for (int j = 0; j < 4; j++) acc[i][j] = 0.f;
    for (int jx = 0; jx < 64; jx++) {
        float a[4], bb[4];
#pragma unroll
        for (int i = 0; i < 4; i++) a[i] = Ss[(tm * 4 + i) * 65 + jx];
#pragma unroll
        for (int j = 0; j < 4; j++) bb[j] = Ks[jx * 65 + tn * 4 + j];
#pragma unroll
        for (int i = 0; i < 4; i++)
#pragma unroll
            for (int j = 0; j < 4; j++) acc[i][j] += a[i] * bb[j];
    }
    for (int px = 0; px < 64; px++) {
        float a[4], bb[4];
#pragma unroll
        for (int i = 0; i < 4; i++) a[i] = Qs[(tm * 4 + i) * 65 + px];
#pragma unroll
        for (int j = 0; j < 4; j++) bb[j] = Hs[px * 65 + tn * 4 + j];
#pragma unroll
        for (int i = 0; i < 4; i++)
#pragma unroll
            for (int j = 0; j < 4; j++) acc[i][j] += a[i] * bb[j];
    }
    // fused combine
#pragma unroll
    for (int i = 0; i < 4; i++) {
        size_t off = rowbase + (size_t)(tm * 4 + i) * DD + tn * 4;
#pragma unroll
        for (int j = 0; j < 4; j++) {
            float gv = g_gate[off + j];
            float xt = g_xt[off + j];
            g_comb[off + j] = gv * acc[i][j] + (1.0f - gv) * xt;
        }
    }
}

// ---------------- launch ----------------
extern "C" void kernel_launch(void* const* d_in, const int* in_sizes, int n_in,
                              void* d_out, int out_size) {
    const float* x   = (const float*)d_in[0];
    const float* stu = (const float*)d_in[1];
    const float* Mi  = (const float*)d_in[2];
    const float* Mf  = (const float*)d_in[3];
    const float* Wq  = (const float*)d_in[4];
    const float* bq  = (const float*)d_in[5];
    const float* Wk  = (const float*)d_in[6];
    const float* bk  = (const float*)d_in[7];
    const float* Wv  = (const float*)d_in[8];
    const float* bv  = (const float*)d_in[9];
    const float* Wg  = (const float*)d_in[10];
    const float* bg  = (const float*)d_in[11];
    const float* Wo  = (const float*)d_in[12];
    const float* bo  = (const float*)d_in[13];
    const float* lnw = (const float*)d_in[14];
    const float* lnb = (const float*)d_in[15];
    float* out = (float*)d_out;

    float *p_q, *p_k, *p_v, *p_gate, *p_comb;
    cudaGetSymbolAddress((void**)&p_q,     g_q);
    cudaGetSymbolAddress((void**)&p_k,     g_k);
    cudaGetSymbolAddress((void**)&p_v,     g_v);
    cudaGetSymbolAddress((void**)&p_gate,  g_gate);
    cudaGetSymbolAddress((void**)&p_comb,  g_comb);

    const int M = BD * TT;  // 2048

    // 1. filter projection + Mi transpose (tiny)
    phi_kernel<<<(T2 * DD + 255) / 256, 256>>>(stu, Mf);
    transpose_kernel<<<dim3(16, 16), dim3(32, 8)>>>(Mi);

    // 2. all five input projections in one launch
    proj_kernel<<<dim3(DD / 64, M / 128, 5), 256>>>(
        x, Wq, Wk, Wv, Wg, bq, bk, bv, bg, p_q, p_k, p_v, p_gate);

    // 3. causal conv (parity split, register sliding window)
    conv_kernel<<<dim3(DD / 64, T2 / 64, BD * 2), dim3(64, 4)>>>();

    // 4. layernorm -> x_tilde
    ln_kernel<<<M, 128>>>(lnw, lnb);

    // 5. chunked linear attention (+ fused combine)
    attn_state_kernel<<<dim3(NCH, NH, BD), 256>>>();
    attn_scan_kernel<<<256, 256>>>();
    static const int attn_smem = 5 * 64 * 65 * 4;
    cudaFuncSetAttribute(attn_out_kernel, cudaFuncAttributeMaxDynamicSharedMemorySize, attn_smem);
    attn_out_kernel<<<dim3(NCH, NH, BD), 256, attn_smem>>>();

    // 6. output projection
    gemm_tf32_kernel<<<dim3(DD / 64, M / 128), 256>>>(p_comb, Wo, bo, out, 0);
}